// round 2
// baseline (speedup 1.0000x reference)
#include <cuda_runtime.h>
#include <cuda_bf16.h>

#define EPS 0.0001f
#define N_DIFFS 4194304

__device__ __forceinline__ float sigmoidf_(float x) {
    return 1.0f / (1.0f + __expf(-x));
}

__device__ __forceinline__ float piecewise_perf(float lb, float ub, float inv_den, float x) {
    // ramp = (ub - x) / (ub - lb + EPS); x<=lb -> 1; x>ub -> 0
    float ramp = (ub - x) * inv_den;
    float r = (x <= lb) ? 1.0f : ramp;
    r = (x > ub) ? 0.0f : r;
    return r;
}

__global__ void __launch_bounds__(256, 6)
perf_model_kernel(const float* __restrict__ bin_centers,
                  const int*   __restrict__ obs_idx,
                  const float* __restrict__ lb1p,
                  const float* __restrict__ ub1p,
                  const float* __restrict__ lb2p,
                  const float* __restrict__ ub2p,
                  const float* __restrict__ respp,
                  float* __restrict__ out)
{
    // uniform scalar prep (identical across all threads; ptxas hoists to UR)
    float a1 = __ldg(lb1p), b1 = __ldg(ub1p);
    float a2 = __ldg(lb2p), b2 = __ldg(ub2p);
    float nlb1 = sigmoidf_(fminf(a1, b1));
    float nub1 = sigmoidf_(fmaxf(a1, b1));
    float nlb2 = sigmoidf_(fminf(a2, b2));
    float nub2 = sigmoidf_(fmaxf(a2, b2));
    float r    = sigmoidf_(__ldg(respp));
    float inv1 = __frcp_rn(nub1 - nlb1 + EPS);
    float inv2 = __frcp_rn(nub2 - nlb2 + EPS);

    int t = blockIdx.x * blockDim.x + threadIdx.x;   // one thread = 8 rows
    long long base_row = (long long)t * 8;
    if (base_row >= N_DIFFS) return;

    // 8 rows * 3 ints = 24 ints = 6 x int4, 16B aligned (offset 96*t bytes)
    const int4* p = reinterpret_cast<const int4*>(obs_idx + base_row * 3);
    // front-batched streaming loads: MLP_p1 = 6
    int4 v0 = __ldcs(p + 0);
    int4 v1 = __ldcs(p + 1);
    int4 v2 = __ldcs(p + 2);
    int4 v3 = __ldcs(p + 3);
    int4 v4 = __ldcs(p + 4);
    int4 v5 = __ldcs(p + 5);

    // row k uses elements (3k, 3k+1); element 3k+2 unused
    // e0..e23 packed into v0..v5
    float x0a = __ldg(bin_centers + v0.x), x0b = __ldg(bin_centers + v0.y);  // r0: e0,e1
    float x1a = __ldg(bin_centers + v0.w), x1b = __ldg(bin_centers + v1.x);  // r1: e3,e4
    float x2a = __ldg(bin_centers + v1.z), x2b = __ldg(bin_centers + v1.w);  // r2: e6,e7
    float x3a = __ldg(bin_centers + v2.y), x3b = __ldg(bin_centers + v2.z);  // r3: e9,e10
    float x4a = __ldg(bin_centers + v3.x), x4b = __ldg(bin_centers + v3.y);  // r4: e12,e13
    float x5a = __ldg(bin_centers + v3.w), x5b = __ldg(bin_centers + v4.x);  // r5: e15,e16
    float x6a = __ldg(bin_centers + v4.z), x6b = __ldg(bin_centers + v4.w);  // r6: e18,e19
    float x7a = __ldg(bin_centers + v5.y), x7b = __ldg(bin_centers + v5.z);  // r7: e21,e22

    float4 oA, oB;
    oA.x = piecewise_perf(nlb1, nub1, inv1, x0a) * piecewise_perf(nlb2, nub2, inv2, x0b) * r;
    oA.y = piecewise_perf(nlb1, nub1, inv1, x1a) * piecewise_perf(nlb2, nub2, inv2, x1b) * r;
    oA.z = piecewise_perf(nlb1, nub1, inv1, x2a) * piecewise_perf(nlb2, nub2, inv2, x2b) * r;
    oA.w = piecewise_perf(nlb1, nub1, inv1, x3a) * piecewise_perf(nlb2, nub2, inv2, x3b) * r;
    oB.x = piecewise_perf(nlb1, nub1, inv1, x4a) * piecewise_perf(nlb2, nub2, inv2, x4b) * r;
    oB.y = piecewise_perf(nlb1, nub1, inv1, x5a) * piecewise_perf(nlb2, nub2, inv2, x5b) * r;
    oB.z = piecewise_perf(nlb1, nub1, inv1, x6a) * piecewise_perf(nlb2, nub2, inv2, x6b) * r;
    oB.w = piecewise_perf(nlb1, nub1, inv1, x7a) * piecewise_perf(nlb2, nub2, inv2, x7b) * r;

    float4* op = reinterpret_cast<float4*>(out) + (long long)t * 2;
    __stcs(op + 0, oA);
    __stcs(op + 1, oB);
}

extern "C" void kernel_launch(void* const* d_in, const int* in_sizes, int n_in,
                              void* d_out, int out_size)
{
    // metadata order: bin_centers, obs_idx, lb1, ub1, lb2, ub2, resp
    const float* bin_centers = (const float*)d_in[0];
    const int*   obs_idx     = (const int*)  d_in[1];
    const float* lb1         = (const float*)d_in[2];
    const float* ub1         = (const float*)d_in[3];
    const float* lb2         = (const float*)d_in[4];
    const float* ub2         = (const float*)d_in[5];
    const float* resp        = (const float*)d_in[6];
    float* out = (float*)d_out;

    const int rows_per_thread = 8;
    const int threads = 256;
    int n_threads = N_DIFFS / rows_per_thread;           // 524,288
    int blocks = (n_threads + threads - 1) / threads;    // 2048

    perf_model_kernel<<<blocks, threads>>>(bin_centers, obs_idx,
                                           lb1, ub1, lb2, ub2, resp, out);
}

// round 3
// speedup vs baseline: 1.1170x; 1.1170x over previous
#include <cuda_runtime.h>
#include <cuda_bf16.h>

#define EPS 0.0001f
#define N_DIFFS 4194304
#define N_BINS 1000

__device__ __forceinline__ float sigmoidf_(float x) {
    return 1.0f / (1.0f + __expf(-x));
}

__device__ __forceinline__ float piecewise_perf(float lb, float ub, float inv_den, float x) {
    // ramp = (ub - x) / (ub - lb + EPS); x<=lb -> 1; x>ub -> 0
    float ramp = (ub - x) * inv_den;
    float r = (x <= lb) ? 1.0f : ramp;
    r = (x > ub) ? 0.0f : r;
    return r;
}

__global__ void __launch_bounds__(256, 8)
perf_model_kernel(const float* __restrict__ bin_centers,
                  const int*   __restrict__ obs_idx,
                  const float* __restrict__ lb1p,
                  const float* __restrict__ ub1p,
                  const float* __restrict__ lb2p,
                  const float* __restrict__ ub2p,
                  const float* __restrict__ respp,
                  float* __restrict__ out)
{
    __shared__ float s_bc[N_BINS];
    // cooperative table stage: 1000 floats / 256 threads = 4 iters (L2-hit)
    for (int i = threadIdx.x; i < N_BINS; i += 256)
        s_bc[i] = __ldg(bin_centers + i);

    // uniform scalar prep (identical across all threads; ptxas hoists to UR)
    float a1 = __ldg(lb1p), b1 = __ldg(ub1p);
    float a2 = __ldg(lb2p), b2 = __ldg(ub2p);
    float nlb1 = sigmoidf_(fminf(a1, b1));
    float nub1 = sigmoidf_(fmaxf(a1, b1));
    float nlb2 = sigmoidf_(fminf(a2, b2));
    float nub2 = sigmoidf_(fmaxf(a2, b2));
    float r    = sigmoidf_(__ldg(respp));
    float inv1 = __frcp_rn(nub1 - nlb1 + EPS);
    float inv2 = __frcp_rn(nub2 - nlb2 + EPS);

    int t = blockIdx.x * blockDim.x + threadIdx.x;   // one thread = 4 rows
    long long base_row = (long long)t * 4;

    // 4 rows * 3 ints = 12 ints = 3 x int4, 16B aligned (offset 48*t bytes)
    const int4* p = reinterpret_cast<const int4*>(obs_idx + base_row * 3);
    int4 v0 = __ldg(p + 0);
    int4 v1 = __ldg(p + 1);
    int4 v2 = __ldg(p + 2);

    __syncthreads();   // table ready (overlapped with the idx loads above)

    // row k uses elements (3k, 3k+1); element 3k+2 unused
    float x0a = s_bc[v0.x], x0b = s_bc[v0.y];   // r0: e0,e1
    float x1a = s_bc[v0.w], x1b = s_bc[v1.x];   // r1: e3,e4
    float x2a = s_bc[v1.z], x2b = s_bc[v1.w];   // r2: e6,e7
    float x3a = s_bc[v2.y], x3b = s_bc[v2.z];   // r3: e9,e10

    float4 o;
    o.x = piecewise_perf(nlb1, nub1, inv1, x0a) * piecewise_perf(nlb2, nub2, inv2, x0b) * r;
    o.y = piecewise_perf(nlb1, nub1, inv1, x1a) * piecewise_perf(nlb2, nub2, inv2, x1b) * r;
    o.z = piecewise_perf(nlb1, nub1, inv1, x2a) * piecewise_perf(nlb2, nub2, inv2, x2b) * r;
    o.w = piecewise_perf(nlb1, nub1, inv1, x3a) * piecewise_perf(nlb2, nub2, inv2, x3b) * r;

    reinterpret_cast<float4*>(out)[t] = o;
}

extern "C" void kernel_launch(void* const* d_in, const int* in_sizes, int n_in,
                              void* d_out, int out_size)
{
    // metadata order: bin_centers, obs_idx, lb1, ub1, lb2, ub2, resp
    const float* bin_centers = (const float*)d_in[0];
    const int*   obs_idx     = (const int*)  d_in[1];
    const float* lb1         = (const float*)d_in[2];
    const float* ub1         = (const float*)d_in[3];
    const float* lb2         = (const float*)d_in[4];
    const float* ub2         = (const float*)d_in[5];
    const float* resp        = (const float*)d_in[6];
    float* out = (float*)d_out;

    const int rows_per_thread = 4;
    const int threads = 256;
    int n_threads = N_DIFFS / rows_per_thread;           // 1,048,576
    int blocks = (n_threads + threads - 1) / threads;    // 4096

    perf_model_kernel<<<blocks, threads>>>(bin_centers, obs_idx,
                                           lb1, ub1, lb2, ub2, resp, out);
}

// round 4
// speedup vs baseline: 1.1233x; 1.0057x over previous
#include <cuda_runtime.h>
#include <cuda_bf16.h>

#define EPS 0.0001f
#define N_DIFFS 4194304
#define N_BINS 1000

__global__ void __launch_bounds__(256, 8)
perf_model_kernel(const float* __restrict__ bin_centers,
                  const int*   __restrict__ obs_idx,
                  const float* __restrict__ lb1p,
                  const float* __restrict__ ub1p,
                  const float* __restrict__ lb2p,
                  const float* __restrict__ ub2p,
                  const float* __restrict__ respp,
                  float* __restrict__ out)
{
    __shared__ float s_bc[N_BINS];
    __shared__ float s_par[8];

    int tid = threadIdx.x;
    // cooperative table stage: 1000 floats / 256 threads = 4 iters
    for (int i = tid; i < N_BINS; i += 256)
        s_bc[i] = __ldg(bin_centers + i);

    // scalar prep ONCE per block (thread 0), overlapped with table fill
    if (tid == 0) {
        float a1 = *lb1p, b1 = *ub1p;
        float a2 = *lb2p, b2 = *ub2p;
        float lo1 = fminf(a1, b1), hi1 = fmaxf(a1, b1);
        float lo2 = fminf(a2, b2), hi2 = fmaxf(a2, b2);
        float nlb1 = 1.0f / (1.0f + expf(-lo1));
        float nub1 = 1.0f / (1.0f + expf(-hi1));
        float nlb2 = 1.0f / (1.0f + expf(-lo2));
        float nub2 = 1.0f / (1.0f + expf(-hi2));
        float r    = 1.0f / (1.0f + expf(-(*respp)));
        float inv1 = 1.0f / (nub1 - nlb1 + EPS);
        float inv2 = 1.0f / (nub2 - nlb2 + EPS);
        s_par[0] = inv1;
        s_par[1] = nub1 * inv1;   // c1
        s_par[2] = inv2;
        s_par[3] = nub2 * inv2;   // c2
        s_par[4] = r;
        s_par[5] = 0.f; s_par[6] = 0.f; s_par[7] = 0.f;
    }

    int t = blockIdx.x * blockDim.x + tid;           // one thread = 4 rows
    long long base_row = (long long)t * 4;

    // 4 rows * 3 ints = 12 ints = 3 x int4, 16B aligned (offset 48*t bytes)
    const int4* p = reinterpret_cast<const int4*>(obs_idx + base_row * 3);
    int4 v0 = __ldg(p + 0);
    int4 v1 = __ldg(p + 1);
    int4 v2 = __ldg(p + 2);

    __syncthreads();   // table + params ready (overlapped with idx loads)

    float4 par = *reinterpret_cast<const float4*>(s_par);   // inv1, c1, inv2, c2
    float r = s_par[4];

    // row k uses elements (3k, 3k+1); element 3k+2 unused
    float x0a = s_bc[v0.x], x0b = s_bc[v0.y];   // r0
    float x1a = s_bc[v0.w], x1b = s_bc[v1.x];   // r1
    float x2a = s_bc[v1.z], x2b = s_bc[v1.w];   // r2
    float x3a = s_bc[v2.y], x3b = s_bc[v2.z];   // r3

    // perf factor = saturate((ub - x) * inv) = saturate(fma(-x, inv, ub*inv))
    float4 o;
    o.x = __saturatef(fmaf(-x0a, par.x, par.y)) * __saturatef(fmaf(-x0b, par.z, par.w)) * r;
    o.y = __saturatef(fmaf(-x1a, par.x, par.y)) * __saturatef(fmaf(-x1b, par.z, par.w)) * r;
    o.z = __saturatef(fmaf(-x2a, par.x, par.y)) * __saturatef(fmaf(-x2b, par.z, par.w)) * r;
    o.w = __saturatef(fmaf(-x3a, par.x, par.y)) * __saturatef(fmaf(-x3b, par.z, par.w)) * r;

    reinterpret_cast<float4*>(out)[t] = o;
}

extern "C" void kernel_launch(void* const* d_in, const int* in_sizes, int n_in,
                              void* d_out, int out_size)
{
    // metadata order: bin_centers, obs_idx, lb1, ub1, lb2, ub2, resp
    const float* bin_centers = (const float*)d_in[0];
    const int*   obs_idx     = (const int*)  d_in[1];
    const float* lb1         = (const float*)d_in[2];
    const float* ub1         = (const float*)d_in[3];
    const float* lb2         = (const float*)d_in[4];
    const float* ub2         = (const float*)d_in[5];
    const float* resp        = (const float*)d_in[6];
    float* out = (float*)d_out;

    const int rows_per_thread = 4;
    const int threads = 256;
    int n_threads = N_DIFFS / rows_per_thread;           // 1,048,576
    int blocks = (n_threads + threads - 1) / threads;    // 4096

    perf_model_kernel<<<blocks, threads>>>(bin_centers, obs_idx,
                                           lb1, ub1, lb2, ub2, resp, out);
}

// round 5
// speedup vs baseline: 1.2759x; 1.1358x over previous
#include <cuda_runtime.h>
#include <cuda_bf16.h>

#define EPS 0.0001f
#define N_DIFFS 4194304

__global__ void __launch_bounds__(256, 8)
perf_model_kernel(const float* __restrict__ bin_centers,
                  const int*   __restrict__ obs_idx,
                  const float* __restrict__ lb1p,
                  const float* __restrict__ ub1p,
                  const float* __restrict__ lb2p,
                  const float* __restrict__ ub2p,
                  const float* __restrict__ respp,
                  float* __restrict__ out)
{
    int t = blockIdx.x * blockDim.x + threadIdx.x;   // one thread = 4 rows
    long long base_row = (long long)t * 4;

    // 4 rows * 3 ints = 12 ints = 3 x int4, 16B aligned (offset 48*t bytes)
    // front-batched: issue the long-latency stream loads FIRST
    const int4* p = reinterpret_cast<const int4*>(obs_idx + base_row * 3);
    int4 v0 = __ldg(p + 0);
    int4 v1 = __ldg(p + 1);
    int4 v2 = __ldg(p + 2);

    // uniform scalar prep (identical across threads; overlaps the LDGs above)
    float a1 = __ldg(lb1p), b1 = __ldg(ub1p);
    float a2 = __ldg(lb2p), b2 = __ldg(ub2p);
    float nlb1 = __frcp_rn(1.0f + __expf(-fminf(a1, b1)));
    float nub1 = __frcp_rn(1.0f + __expf(-fmaxf(a1, b1)));
    float nlb2 = __frcp_rn(1.0f + __expf(-fminf(a2, b2)));
    float nub2 = __frcp_rn(1.0f + __expf(-fmaxf(a2, b2)));
    float r    = __frcp_rn(1.0f + __expf(-__ldg(respp)));
    float inv1 = __frcp_rn(nub1 - nlb1 + EPS);
    float inv2 = __frcp_rn(nub2 - nlb2 + EPS);
    float c1 = nub1 * inv1;
    float c2 = nub2 * inv2;

    // dependent gathers from the L1-resident 4KB table
    float x0a = __ldg(bin_centers + v0.x), x0b = __ldg(bin_centers + v0.y);  // r0
    float x1a = __ldg(bin_centers + v0.w), x1b = __ldg(bin_centers + v1.x);  // r1
    float x2a = __ldg(bin_centers + v1.z), x2b = __ldg(bin_centers + v1.w);  // r2
    float x3a = __ldg(bin_centers + v2.y), x3b = __ldg(bin_centers + v2.z);  // r3

    // perf factor = saturate((ub - x) * inv) = saturate(fma(-x, inv, ub*inv))
    float4 o;
    o.x = __saturatef(fmaf(-x0a, inv1, c1)) * __saturatef(fmaf(-x0b, inv2, c2)) * r;
    o.y = __saturatef(fmaf(-x1a, inv1, c1)) * __saturatef(fmaf(-x1b, inv2, c2)) * r;
    o.z = __saturatef(fmaf(-x2a, inv1, c1)) * __saturatef(fmaf(-x2b, inv2, c2)) * r;
    o.w = __saturatef(fmaf(-x3a, inv1, c1)) * __saturatef(fmaf(-x3b, inv2, c2)) * r;

    reinterpret_cast<float4*>(out)[t] = o;
}

extern "C" void kernel_launch(void* const* d_in, const int* in_sizes, int n_in,
                              void* d_out, int out_size)
{
    // metadata order: bin_centers, obs_idx, lb1, ub1, lb2, ub2, resp
    const float* bin_centers = (const float*)d_in[0];
    const int*   obs_idx     = (const int*)  d_in[1];
    const float* lb1         = (const float*)d_in[2];
    const float* ub1         = (const float*)d_in[3];
    const float* lb2         = (const float*)d_in[4];
    const float* ub2         = (const float*)d_in[5];
    const float* resp        = (const float*)d_in[6];
    float* out = (float*)d_out;

    const int rows_per_thread = 4;
    const int threads = 256;
    int n_threads = N_DIFFS / rows_per_thread;           // 1,048,576
    int blocks = (n_threads + threads - 1) / threads;    // 4096

    perf_model_kernel<<<blocks, threads>>>(bin_centers, obs_idx,
                                           lb1, ub1, lb2, ub2, resp, out);
}